// round 16
// baseline (speedup 1.0000x reference)
#include <cuda_runtime.h>
#include <cuda_fp16.h>
#include <math.h>

#define NB    4
#define NS    160
#define NSS   (160*160)
#define NVOX  (160*160*160)
#define ZCH   40
#define NBLK1 640          // pass-1 blocks: 40*4*NB
#define NBLK2 640          // pass-2 blocks: 40*4*NB

// 1D gaussian taps, sigma=5, radius=4: exp(-i^2/50)
#define G_TAPS {0.72614904f,0.83527021f,0.92311635f,0.98019867f,1.0f,\
                0.98019867f,0.92311635f,0.83527021f,0.72614904f}

__device__ __forceinline__ __half2 u32_as_h2(unsigned u) {
    return *reinterpret_cast<__half2*>(&u);
}

__device__ __half2  g_q[(size_t)NB * NVOX / 2];   // (K_x*K_z*p), half2 per x-pair
__device__ unsigned g_pv8[(size_t)NB * NVOX / 2]; // 2 voxels/u32: p0|v0<<8|p1<<16|v1<<24 (u8)
__device__ double   g_p1[NB * 160 * 3];           // pass-1 per-block (sp, sip, si)
__device__ float2   g_means[NB];                  // (m0, m1) per batch
__device__ double   g_p2[NBLK2 * 4];              // pass-2 per-block (N0,D0,N1,D1)
__device__ unsigned g_cntA = 0;                   // pass-1 finalize counter
__device__ unsigned g_cnt  = 0;                   // pass-2 finalize counter

// conv-of-ones along one axis (zero padding): closed form
__device__ __forceinline__ float cfun(int i) {
    const float H[5] = {1.0f, 1.98019867f, 2.90331502f, 3.73858523f, 4.46473427f};
    int a = i < 4 ? i : 4;
    int c = (159 - i) < 4 ? (159 - i) : 4;
    return H[a] + H[c] - 1.0f;
}

// Pass 1: stream lab/inp along z. Per z: mean sums, u8 (p,v) pack, z-conv
// (fp16 ring), smem row, x-conv (paired taps) -> zx-convolved q (fp16).
// Last block computes per-batch means.
__global__ void __launch_bounds__(320) k_A(const float* __restrict__ lab,
                                           const float* __restrict__ inp) {
    const float G[9] = G_TAPS;
    __half2 G2[9];
    #pragma unroll
    for (int i = 0; i < 9; i++) G2[i] = __float2half2_rn(G[i]);
    __half2 TE[5], TO[5];
    TE[0] = __floats2half2_rn(G[0], G[1]); TE[1] = __floats2half2_rn(G[2], G[3]);
    TE[2] = __floats2half2_rn(G[4], G[5]); TE[3] = __floats2half2_rn(G[6], G[7]);
    TE[4] = __floats2half2_rn(G[8], 0.f);
    TO[0] = __floats2half2_rn(0.f, G[0]);  TO[1] = __floats2half2_rn(G[1], G[2]);
    TO[2] = __floats2half2_rn(G[3], G[4]); TO[3] = __floats2half2_rn(G[5], G[6]);
    TO[4] = __floats2half2_rn(G[7], G[8]);

    int hx = threadIdx.x;                 // 0..79 (x pair)
    int ty = threadIdx.y;                 // 0..3
    int y  = blockIdx.x * 4 + ty;
    int z0 = blockIdx.y * ZCH;
    int b  = blockIdx.z;
    int tid = ty * 80 + hx;

    size_t rowbase = (size_t)b * NVOX + (size_t)y * NS;
    const float2* Lp = (const float2*)(lab + rowbase) + hx;
    const float2* Vp = (const float2*)(inp + rowbase) + hx;
    unsigned* PV = g_pv8 + rowbase / 2 + hx;           // u32 = 2 voxels; 80/row
    __half2*  Q  = g_q   + rowbase / 2 + hx;           // half2 = 2 x; 80/row

    __shared__ __half2 srow[4][2][84];    // [ty][buf][hx+2], pads at 0,1,82,83
    const __half2 h2z = __float2half2_rn(0.f);
    if (hx < 2) {
        srow[ty][0][hx] = h2z;       srow[ty][1][hx] = h2z;
        srow[ty][0][82 + hx] = h2z;  srow[ty][1][82 + hx] = h2z;
    }

    __half2 ring[9];
    #pragma unroll
    for (int i = 0; i < 8; i++) {
        int z = z0 - 4 + i;
        float2 f = make_float2(0.f, 0.f);
        if (z >= 0) f = Lp[(size_t)z * (NSS / 2)];
        ring[i] = __floats2half2_rn(f.x, f.y);
    }

    float sp = 0.f, sip = 0.f, si = 0.f;

    #pragma unroll 8
    for (int j = 0; j < ZCH; ++j) {
        int z  = z0 + j;
        int zl = z + 4;
        float2 f = make_float2(0.f, 0.f);
        if (zl < NS) f = Lp[(size_t)zl * (NSS / 2)];
        ring[8] = __floats2half2_rn(f.x, f.y);

        // sums + u8 (p,v) pack at current z (ring[4] holds p)
        float2 vc = Vp[(size_t)z * (NSS / 2)];
        float2 pc = __half22float2(ring[4]);
        sp  += pc.x + pc.y;
        sip += vc.x * pc.x + vc.y * pc.y;
        si  += vc.x + vc.y;
        unsigned pu0 = __float2uint_rn(pc.x * 255.f);
        unsigned vu0 = __float2uint_rn(vc.x * 255.f);
        unsigned pu1 = __float2uint_rn(pc.y * 255.f);
        unsigned vu1 = __float2uint_rn(vc.y * 255.f);
        PV[(size_t)z * (NSS / 2)] = pu0 | (vu0 << 8) | (pu1 << 16) | (vu1 << 24);

        // z-conv
        __half2 s = __hmul2(G2[0], ring[0]);
        #pragma unroll
        for (int i = 1; i < 9; i++) s = __hfma2(G2[i], ring[i], s);

        int bf = j & 1;
        srow[ty][bf][hx + 2] = s;
        __syncthreads();

        // x-conv (even/odd paired taps on half2 row)
        __half2 h0 = srow[ty][bf][hx + 0];
        __half2 h1 = srow[ty][bf][hx + 1];
        __half2 h2 = srow[ty][bf][hx + 2];
        __half2 h3 = srow[ty][bf][hx + 3];
        __half2 h4 = srow[ty][bf][hx + 4];
        __half2 se = __hmul2(TE[0], h0);
        se = __hfma2(TE[1], h1, se); se = __hfma2(TE[2], h2, se);
        se = __hfma2(TE[3], h3, se); se = __hfma2(TE[4], h4, se);
        __half2 so = __hmul2(TO[0], h0);
        so = __hfma2(TO[1], h1, so); so = __hfma2(TO[2], h2, so);
        so = __hfma2(TO[3], h3, so); so = __hfma2(TO[4], h4, so);
        float2 fe = __half22float2(se);
        float2 fo = __half22float2(so);
        Q[(size_t)z * (NSS / 2)] = __floats2half2_rn(fe.x + fe.y, fo.x + fo.y);

        #pragma unroll
        for (int i = 0; i < 8; i++) ring[i] = ring[i + 1];
    }

    // block-reduce sums -> slot; last block computes per-batch means
    double a = sp, c = sip, d = si;
    #pragma unroll
    for (int o = 16; o > 0; o >>= 1) {
        a += __shfl_down_sync(0xffffffffu, a, o);
        c += __shfl_down_sync(0xffffffffu, c, o);
        d += __shfl_down_sync(0xffffffffu, d, o);
    }
    __shared__ double sm[3][10];
    int w = tid >> 5, l = tid & 31;
    if (l == 0) { sm[0][w] = a; sm[1][w] = c; sm[2][w] = d; }
    __syncthreads();
    __shared__ int s_lastA;
    if (tid == 0) {
        double aa = 0, cc = 0, dd = 0;
        for (int i = 0; i < 10; i++) { aa += sm[0][i]; cc += sm[1][i]; dd += sm[2][i]; }
        int pb = ((b * 4 + blockIdx.y) * 40 + blockIdx.x) * 3;
        g_p1[pb + 0] = aa;
        g_p1[pb + 1] = cc;
        g_p1[pb + 2] = dd;
        __threadfence();
        unsigned t = atomicAdd(&g_cntA, 1);
        s_lastA = (t == NBLK1 - 1);
    }
    __syncthreads();
    if (s_lastA) {
        if (tid == 0) g_cntA = 0;
        if (w < 4) {                      // warp w handles batch w
            double aa = 0, cc = 0, dd = 0;
            for (int i = l; i < 160; i += 32) {
                int base = (w * 160 + i) * 3;
                aa += g_p1[base + 0]; cc += g_p1[base + 1]; dd += g_p1[base + 2];
            }
            #pragma unroll
            for (int o = 16; o > 0; o >>= 1) {
                aa += __shfl_down_sync(0xffffffffu, aa, o);
                cc += __shfl_down_sync(0xffffffffu, cc, o);
                dd += __shfl_down_sync(0xffffffffu, dd, o);
            }
            if (l == 0) {
                const double Nv = (double)NVOX;
                float m0 = (float)((cc / Nv) / (aa / Nv + 1e-5));
                float m1 = (float)(((dd - cc) / Nv) / ((Nv - aa) / Nv + 1e-5));
                g_means[w] = make_float2(m0, m1);
            }
        }
    }
}

// Pass 2: barrier-free streaming, 2 x per thread (80 tx). Single half2 ring
// chain over y on q with next-row prefetch; decode u8 (p,v); 4 dots.
// p kept unscaled (x255) in numerator accumulators; divided once at the end.
__global__ void __launch_bounds__(320) k_C(float* __restrict__ out) {
    const float G[9] = G_TAPS;
    __half2 G2[9];
    #pragma unroll
    for (int i = 0; i < 9; i++) G2[i] = __float2half2_rn(G[i]);

    int tx = threadIdx.x;          // 0..79 (x pair: 2tx, 2tx+1)
    int tz = threadIdx.y;          // 0..3
    int z  = blockIdx.x * 4 + tz;
    int y0 = blockIdx.y * ZCH;
    int b  = blockIdx.z;
    int tid = tz * 80 + tx;

    float2 mm = g_means[b];
    float m0 = mm.x, m1 = mm.y;

    float cz  = cfun(z);
    float cc0 = cfun(2 * tx + 0) * cz;
    float cc1 = cfun(2 * tx + 1) * cz;

    const int QS = NS / 2;   // 80: u32 per q row; u32 per pv row
    size_t plane = (size_t)b * NVOX + (size_t)z * NSS;
    const unsigned* Qr  = (const unsigned*)g_q + plane / 2 + tx;
    const unsigned* PVr = g_pv8 + plane / 2 + tx;

    __half2 r[9];
    const __half2 h2z = __float2half2_rn(0.f);
    #pragma unroll
    for (int i = 0; i < 8; i++) {
        int yy = y0 - 4 + i;
        r[i] = (yy >= 0) ? u32_as_h2(Qr[(size_t)yy * QS]) : h2z;
    }

    // primed loads for j=0
    unsigned qw = 0u;
    { int yl = y0 + 4; if (yl < NS) qw = Qr[(size_t)yl * QS]; }
    unsigned pvw = PVr[(size_t)y0 * QS];

    float aD0 = 0.f, aN0 = 0.f, aD1 = 0.f, aN1 = 0.f;
    const float INV255 = 1.f / 255.f;

    #pragma unroll 8
    for (int j = 0; j < ZCH; ++j) {
        int y = y0 + j;

        // prefetch next row
        unsigned qw_n = 0u;
        int yn = y + 5;
        if (yn < NS) qw_n = Qr[(size_t)yn * QS];
        int yp = y + 1; if (yp > NS - 1) yp = NS - 1;
        unsigned pvw_n = PVr[(size_t)yp * QS];

        r[8] = u32_as_h2(qw);

        __half2 s0 = __hmul2(G2[0], r[0]);
        #pragma unroll
        for (int i = 1; i < 9; i++) s0 = __hfma2(G2[i], r[i], s0);
        float2 qa = __half22float2(s0);

        float cy = cfun(y);
        float qc0 = cc0 * cy - qa.x;
        float qc1 = cc1 * cy - qa.y;

        #define LANE(pu, vu, qv, qcv) { \
            float vf = __uint2float_rn(vu); \
            float pf = __uint2float_rn(pu); \
            float d0 = fmaf(vf, INV255, -m0); float u0 = d0 * d0; float w0 = __expf(-u0 * u0); \
            float d1 = fmaf(vf, INV255, -m1); float u1 = d1 * d1; float w1 = __expf(-u1 * u1); \
            aD0 += w0 * qv;  aN0 += (pf * w0) * qv; \
            aD1 += w1 * qcv; aN1 += ((255.f - pf) * w1) * qcv; }
        LANE((pvw & 0xFFu), ((pvw >> 8) & 0xFFu),  qa.x, qc0)
        LANE(((pvw >> 16) & 0xFFu), (pvw >> 24),   qa.y, qc1)
        #undef LANE

        #pragma unroll
        for (int i = 0; i < 8; i++) r[i] = r[i + 1];
        qw = qw_n; pvw = pvw_n;
    }

    aN0 *= INV255;
    aN1 *= INV255;

    // block-reduce four accumulators, write partial, last block finalizes
    double vn0 = aN0, vd0 = aD0, vn1 = aN1, vd1 = aD1;
    #pragma unroll
    for (int o = 16; o > 0; o >>= 1) {
        vn0 += __shfl_down_sync(0xffffffffu, vn0, o);
        vd0 += __shfl_down_sync(0xffffffffu, vd0, o);
        vn1 += __shfl_down_sync(0xffffffffu, vn1, o);
        vd1 += __shfl_down_sync(0xffffffffu, vd1, o);
    }
    __shared__ double sm[4][10];
    int w = tid >> 5, l = tid & 31;
    if (l == 0) { sm[0][w] = vn0; sm[1][w] = vd0; sm[2][w] = vn1; sm[3][w] = vd1; }
    __syncthreads();

    __shared__ int s_last;
    int bid = (b * 4 + blockIdx.y) * 40 + blockIdx.x;
    if (tid == 0) {
        double aa = 0, bb = 0, cc = 0, dd = 0;
        for (int i = 0; i < 10; i++) { aa += sm[0][i]; bb += sm[1][i]; cc += sm[2][i]; dd += sm[3][i]; }
        g_p2[bid * 4 + 0] = aa;
        g_p2[bid * 4 + 1] = bb;
        g_p2[bid * 4 + 2] = cc;
        g_p2[bid * 4 + 3] = dd;
        __threadfence();
        unsigned t = atomicAdd(&g_cnt, 1);
        s_last = (t == NBLK2 - 1);
    }
    __syncthreads();
    if (s_last) {
        double s0 = 0, s1 = 0, s2 = 0, s3 = 0;
        for (int i = tid; i < NBLK2; i += 320) {
            s0 += g_p2[i * 4 + 0];
            s1 += g_p2[i * 4 + 1];
            s2 += g_p2[i * 4 + 2];
            s3 += g_p2[i * 4 + 3];
        }
        #pragma unroll
        for (int o = 16; o > 0; o >>= 1) {
            s0 += __shfl_down_sync(0xffffffffu, s0, o);
            s1 += __shfl_down_sync(0xffffffffu, s1, o);
            s2 += __shfl_down_sync(0xffffffffu, s2, o);
            s3 += __shfl_down_sync(0xffffffffu, s3, o);
        }
        if (l == 0) { sm[0][w] = s0; sm[1][w] = s1; sm[2][w] = s2; sm[3][w] = s3; }
        __syncthreads();
        if (tid == 0) {
            double aa = 0, bb = 0, cc = 0, dd = 0;
            for (int i = 0; i < 10; i++) { aa += sm[0][i]; bb += sm[1][i]; cc += sm[2][i]; dd += sm[3][i]; }
            double loss = fabs(aa / (bb + 1e-6)) + fabs(cc / (dd + 1e-6));
            out[0] = (float)(2.0 - loss);
            g_cnt = 0;   // reset for next graph replay
        }
    }
}

extern "C" void kernel_launch(void* const* d_in, const int* in_sizes, int n_in,
                              void* d_out, int out_size) {
    const float* lab = (const float*)d_in[0];
    const float* inp = (const float*)d_in[1];
    float* out = (float*)d_out;

    k_A<<<dim3(40, 4, NB), dim3(80, 4)>>>(lab, inp);   // sums + zx-conv(p) + u8 pv + means
    k_C<<<dim3(40, 4, NB), dim3(80, 4)>>>(out);        // y-conv + weights + dots + finalize
}

// round 17
// speedup vs baseline: 1.0643x; 1.0643x over previous
#include <cuda_runtime.h>
#include <cuda_fp16.h>
#include <math.h>

#define NB    4
#define NS    160
#define NSS   (160*160)
#define NVOX  (160*160*160)

#define YT    20                  // output y-rows per block
#define YR    28                  // input y-rows (YT + 8 halo)
#define ZC    20                  // output z-planes per block
#define TXN   80                  // x-pairs per row
#define NYT   8
#define NZC   8
#define NBLKF (NYT*NZC*NB)        // 256 fused blocks
#define NBLKS 120                 // sums blocks per batch

// dynamic smem carve (bytes)
#define SZ_INB   (YR*(TXN+4)*4)   // 9408  raw p plane rows (padded)
#define SZ_XCV   (YR*TXN*4)       // 8960  x-convolved rows
#define SZ_RING  (9*YT*TXN*4)     // 57600 xy-convolved plane ring
#define SZ_PRING (5*YT*TXN*4)     // 32000 raw-p delay ring (center rows)
#define SMEMSZ   (SZ_INB+SZ_XCV+SZ_RING+SZ_PRING)

// 1D gaussian taps, sigma=5, radius=4: exp(-i^2/50)
#define G_TAPS {0.72614904f,0.83527021f,0.92311635f,0.98019867f,1.0f,\
                0.98019867f,0.92311635f,0.83527021f,0.72614904f}

__device__ double   g_p1[NB * NBLKS * 3];   // per-block (sp, sip, si)
__device__ double   g_p2[NBLKF * 4];        // per-block (N0, D0, T1, D1)
__device__ unsigned g_cnt = 0;              // finalize counter (self-resetting)

// conv-of-ones along one axis (zero padding): closed form
__device__ __forceinline__ float cfun(int i) {
    const float H[5] = {1.0f, 1.98019867f, 2.90331502f, 3.73858523f, 4.46473427f};
    int a = i < 4 ? i : 4;
    int c = (NS - 1 - i) < 4 ? (NS - 1 - i) : 4;
    return H[a] + H[c] - 1.0f;
}

// Kernel 1: exact global sums (sp, sip, si) per batch -> per-block slots.
__global__ void __launch_bounds__(256) k_S(const float* __restrict__ lab,
                                           const float* __restrict__ inp) {
    int b = blockIdx.y;
    int tid = threadIdx.x;
    const float4* L = (const float4*)(lab + (size_t)b * NVOX);
    const float4* V = (const float4*)(inp + (size_t)b * NVOX);
    const int N4 = NVOX / 4;
    float sp = 0.f, sip = 0.f, si = 0.f;
    for (int i = blockIdx.x * 256 + tid; i < N4; i += NBLKS * 256) {
        float4 p = L[i];
        float4 v = V[i];
        sp  += (p.x + p.y) + (p.z + p.w);
        sip += (v.x * p.x + v.y * p.y) + (v.z * p.z + v.w * p.w);
        si  += (v.x + v.y) + (v.z + v.w);
    }
    double a = sp, c = sip, d = si;
    #pragma unroll
    for (int o = 16; o > 0; o >>= 1) {
        a += __shfl_down_sync(0xffffffffu, a, o);
        c += __shfl_down_sync(0xffffffffu, c, o);
        d += __shfl_down_sync(0xffffffffu, d, o);
    }
    __shared__ double sm[3][8];
    int w = tid >> 5, l = tid & 31;
    if (l == 0) { sm[0][w] = a; sm[1][w] = c; sm[2][w] = d; }
    __syncthreads();
    if (tid == 0) {
        double aa = 0, cc = 0, dd = 0;
        for (int i = 0; i < 8; i++) { aa += sm[0][i]; cc += sm[1][i]; dd += sm[2][i]; }
        int pb = (b * NBLKS + blockIdx.x) * 3;
        g_p1[pb + 0] = aa;
        g_p1[pb + 1] = cc;
        g_p1[pb + 2] = dd;
    }
}

// Kernel 2 (fused): block-local separable 3D conv of p via smem plane ring,
// immediate weight + dot accumulation. No intermediate global fields.
__global__ void __launch_bounds__(320, 2) k_F(const float* __restrict__ lab,
                                              const float* __restrict__ inp,
                                              float* __restrict__ out) {
    const float G[9] = G_TAPS;
    __half2 G2[9];
    #pragma unroll
    for (int i = 0; i < 9; i++) G2[i] = __float2half2_rn(G[i]);
    __half2 TE[5], TO[5];
    TE[0] = __floats2half2_rn(G[0], G[1]); TE[1] = __floats2half2_rn(G[2], G[3]);
    TE[2] = __floats2half2_rn(G[4], G[5]); TE[3] = __floats2half2_rn(G[6], G[7]);
    TE[4] = __floats2half2_rn(G[8], 0.f);
    TO[0] = __floats2half2_rn(0.f, G[0]);  TO[1] = __floats2half2_rn(G[1], G[2]);
    TO[2] = __floats2half2_rn(G[3], G[4]); TO[3] = __floats2half2_rn(G[5], G[6]);
    TO[4] = __floats2half2_rn(G[7], G[8]);

    extern __shared__ __align__(16) char dsm[];
    __half2 (*inb)[TXN + 4]     = (__half2 (*)[TXN + 4])(dsm);
    __half2 (*xcv)[TXN]         = (__half2 (*)[TXN])(dsm + SZ_INB);
    __half2 (*ring)[YT][TXN]    = (__half2 (*)[YT][TXN])(dsm + SZ_INB + SZ_XCV);
    __half2 (*pring)[YT][TXN]   = (__half2 (*)[YT][TXN])(dsm + SZ_INB + SZ_XCV + SZ_RING);

    int tx  = threadIdx.x;            // 0..79 (x pair 2tx, 2tx+1)
    int ty  = threadIdx.y;            // 0..3
    int tid = ty * TXN + tx;
    int gy0 = blockIdx.x * YT;
    int z0  = blockIdx.y * ZC;
    int b   = blockIdx.z;

    // means from k_S partials (warp 0)
    __shared__ float s_m[2];
    if (tid < 32) {
        double a = 0, c = 0, d = 0;
        for (int i = tid; i < NBLKS; i += 32) {
            int base = (b * NBLKS + i) * 3;
            a += g_p1[base + 0]; c += g_p1[base + 1]; d += g_p1[base + 2];
        }
        #pragma unroll
        for (int o = 16; o > 0; o >>= 1) {
            a += __shfl_down_sync(0xffffffffu, a, o);
            c += __shfl_down_sync(0xffffffffu, c, o);
            d += __shfl_down_sync(0xffffffffu, d, o);
        }
        if (tid == 0) {
            const double Nv = (double)NVOX;
            s_m[0] = (float)((c / Nv) / (a / Nv + 1e-5));
            s_m[1] = (float)(((d - c) / Nv) / ((Nv - a) / Nv + 1e-5));
        }
    }
    // zero the x pads of inb (columns 0,1 and 82,83), never rewritten
    if (tx < 2) {
        const __half2 h2z = __float2half2_rn(0.f);
        for (int r = ty; r < YR; r += 4) { inb[r][tx] = h2z; inb[r][TXN + 2 + tx] = h2z; }
    }
    __syncthreads();
    float m0 = s_m[0], m1 = s_m[1];

    float cx0 = cfun(2 * tx);
    float cx1 = cfun(2 * tx + 1);
    float cyr[5];
    #pragma unroll
    for (int k = 0; k < 5; k++) cyr[k] = cfun(gy0 + ty + 4 * k);

    const float* labB = lab + (size_t)b * NVOX;
    const float* inpB = inp + (size_t)b * NVOX;

    float aN0 = 0.f, aD0 = 0.f, aT1 = 0.f, aD1 = 0.f;

    #pragma unroll 1
    for (int js = 0; js < ZC + 8; ++js) {
        int z_in = z0 - 4 + js;

        // (a) load raw p plane rows (with y/z halo, zero-padded)
        bool zok = (z_in >= 0) && (z_in < NS);
        #pragma unroll
        for (int k = 0; k < 7; k++) {
            int r  = ty + 4 * k;
            int gy = gy0 - 4 + r;
            float2 f = make_float2(0.f, 0.f);
            if (zok && gy >= 0 && gy < NS)
                f = *((const float2*)(labB + (size_t)z_in * NSS + (size_t)gy * NS) + tx);
            inb[r][2 + tx] = __floats2half2_rn(f.x, f.y);
        }
        __syncthreads();   // BAR1: inb ready (also protects xcv/ring of prev step)

        // (b) x-conv each row; stash center-row raw p into the delay ring
        #pragma unroll
        for (int k = 0; k < 7; k++) {
            int r = ty + 4 * k;
            __half2 h0 = inb[r][tx + 0], h1 = inb[r][tx + 1], h2v = inb[r][tx + 2];
            __half2 h3 = inb[r][tx + 3], h4 = inb[r][tx + 4];
            __half2 se = __hmul2(TE[0], h0);
            se = __hfma2(TE[1], h1, se); se = __hfma2(TE[2], h2v, se);
            se = __hfma2(TE[3], h3, se); se = __hfma2(TE[4], h4, se);
            __half2 so = __hmul2(TO[0], h0);
            so = __hfma2(TO[1], h1, so); so = __hfma2(TO[2], h2v, so);
            so = __hfma2(TO[3], h3, so); so = __hfma2(TO[4], h4, so);
            float2 fe = __half22float2(se), fo = __half22float2(so);
            xcv[r][tx] = __floats2half2_rn(fe.x + fe.y, fo.x + fo.y);
        }
        {
            int ps = (z_in + 5) % 5;
            #pragma unroll
            for (int k = 0; k < 5; k++) {
                int r0 = ty + 4 * k;
                pring[ps][r0][tx] = inb[r0 + 4][tx + 2];
            }
        }
        __syncthreads();   // BAR2: xcv ready

        // (c+d) y-conv into ring (newest plane kept in reg), z-conv, weights+dots
        int sw = (z_in + 9) % 9;
        int z_out = z_in - 4;
        bool out_ok = (js >= 8);
        float cz = out_ok ? cfun(z_out) : 0.f;
        int pr = out_ok ? ((z_out + 5) % 5) : 0;
        int s0 = out_ok ? ((z_out + 5) % 9) : 0;

        #pragma unroll
        for (int k = 0; k < 5; k++) {
            int r0 = ty + 4 * k;
            __half2 acc = __hmul2(G2[0], xcv[r0 + 0][tx]);
            #pragma unroll
            for (int j = 1; j < 9; j++) acc = __hfma2(G2[j], xcv[r0 + j][tx], acc);
            ring[sw][r0][tx] = acc;

            if (out_ok) {
                __half2 qh = __hmul2(G2[8], acc);    // plane z_out+4 (newest)
                #pragma unroll
                for (int j = 0; j < 8; j++) {
                    int sl = s0 + j; if (sl >= 9) sl -= 9;
                    qh = __hfma2(G2[j], ring[sl][r0][tx], qh);
                }
                float2 qf = __half22float2(qh);

                float cyz = cyr[k] * cz;
                float qc0 = fmaf(cx0, cyz, -qf.x);
                float qc1 = fmaf(cx1, cyz, -qf.y);

                float2 pf = __half22float2(pring[pr][r0][tx]);
                float2 vv = *((const float2*)(inpB + (size_t)z_out * NSS + (size_t)(gy0 + r0) * NS) + tx);

                // even lane
                {
                    float d0 = vv.x - m0; float u0 = d0 * d0; float w0 = __expf(-u0 * u0);
                    float d1 = vv.x - m1; float u1 = d1 * d1; float w1 = __expf(-u1 * u1);
                    aD0 += w0 * qf.x;  aN0 += (pf.x * w0) * qf.x;
                    aD1 += w1 * qc0;   aT1 += (pf.x * w1) * qc0;
                }
                // odd lane
                {
                    float d0 = vv.y - m0; float u0 = d0 * d0; float w0 = __expf(-u0 * u0);
                    float d1 = vv.y - m1; float u1 = d1 * d1; float w1 = __expf(-u1 * u1);
                    aD0 += w0 * qf.y;  aN0 += (pf.y * w0) * qf.y;
                    aD1 += w1 * qc1;   aT1 += (pf.y * w1) * qc1;
                }
            }
        }
    }

    // block reduce (N0, D0, T1, D1); last block finalizes (N1 = D1 - T1)
    double vn0 = aN0, vd0 = aD0, vt1 = aT1, vd1 = aD1;
    #pragma unroll
    for (int o = 16; o > 0; o >>= 1) {
        vn0 += __shfl_down_sync(0xffffffffu, vn0, o);
        vd0 += __shfl_down_sync(0xffffffffu, vd0, o);
        vt1 += __shfl_down_sync(0xffffffffu, vt1, o);
        vd1 += __shfl_down_sync(0xffffffffu, vd1, o);
    }
    __shared__ double sm[4][10];
    int w = tid >> 5, l = tid & 31;
    if (l == 0) { sm[0][w] = vn0; sm[1][w] = vd0; sm[2][w] = vt1; sm[3][w] = vd1; }
    __syncthreads();

    __shared__ int s_last;
    int bid = (b * NZC + blockIdx.y) * NYT + blockIdx.x;
    if (tid == 0) {
        double aa = 0, bb = 0, cc = 0, dd = 0;
        for (int i = 0; i < 10; i++) { aa += sm[0][i]; bb += sm[1][i]; cc += sm[2][i]; dd += sm[3][i]; }
        g_p2[bid * 4 + 0] = aa;
        g_p2[bid * 4 + 1] = bb;
        g_p2[bid * 4 + 2] = cc;
        g_p2[bid * 4 + 3] = dd;
        __threadfence();
        unsigned t = atomicAdd(&g_cnt, 1);
        s_last = (t == NBLKF - 1);
    }
    __syncthreads();
    if (s_last) {
        double s0 = 0, s1 = 0, s2 = 0, s3 = 0;
        for (int i = tid; i < NBLKF; i += 320) {
            s0 += g_p2[i * 4 + 0];
            s1 += g_p2[i * 4 + 1];
            s2 += g_p2[i * 4 + 2];
            s3 += g_p2[i * 4 + 3];
        }
        #pragma unroll
        for (int o = 16; o > 0; o >>= 1) {
            s0 += __shfl_down_sync(0xffffffffu, s0, o);
            s1 += __shfl_down_sync(0xffffffffu, s1, o);
            s2 += __shfl_down_sync(0xffffffffu, s2, o);
            s3 += __shfl_down_sync(0xffffffffu, s3, o);
        }
        if (l == 0) { sm[0][w] = s0; sm[1][w] = s1; sm[2][w] = s2; sm[3][w] = s3; }
        __syncthreads();
        if (tid == 0) {
            double N0 = 0, D0 = 0, T1 = 0, D1 = 0;
            for (int i = 0; i < 10; i++) { N0 += sm[0][i]; D0 += sm[1][i]; T1 += sm[2][i]; D1 += sm[3][i]; }
            double N1 = D1 - T1;
            double loss = fabs(N0 / (D0 + 1e-6)) + fabs(N1 / (D1 + 1e-6));
            out[0] = (float)(2.0 - loss);
            g_cnt = 0;   // reset for next graph replay
        }
    }
}

extern "C" void kernel_launch(void* const* d_in, const int* in_sizes, int n_in,
                              void* d_out, int out_size) {
    const float* lab = (const float*)d_in[0];
    const float* inp = (const float*)d_in[1];
    float* out = (float*)d_out;

    cudaFuncSetAttribute(k_F, cudaFuncAttributeMaxDynamicSharedMemorySize, SMEMSZ);

    k_S<<<dim3(NBLKS, NB), 256>>>(lab, inp);                      // exact means sums
    k_F<<<dim3(NYT, NZC, NB), dim3(TXN, 4), SMEMSZ>>>(lab, inp, out);  // conv + dots + finalize
}